// round 13
// baseline (speedup 1.0000x reference)
#include <cuda_runtime.h>
#include <cuda_bf16.h>
#include <mma.h>
#include <cstdint>
#include <math.h>

using namespace nvcuda;

#define B_   2
#define T_   2048
#define C_   512
#define H_   8
#define D_   64
#define BH_  (B_*H_)
#define L_   128
#define NC_  (T_/L_)
#define M_   (B_*T_)
#define EPS_ 1e-8f

// Scratch (device globals)
__device__ float g_kv  [BH_*NC_*D_*D_];
__device__ float g_ks  [BH_*NC_*D_];

// bf16 hi/lo split buffers
__device__ __nv_bfloat16 g_xhi[M_*C_],  g_xlo[M_*C_];
__device__ __nv_bfloat16 g_wqh[C_*3*C_], g_wql[C_*3*C_];
__device__ __nv_bfloat16 g_wph[C_*C_],  g_wpl[C_*C_];
__device__ __nv_bfloat16 g_yhi[M_*C_],  g_ylo[M_*C_];
__device__ __nv_bfloat16 g_qh[BH_*T_*D_], g_ql[BH_*T_*D_];
__device__ __nv_bfloat16 g_kh[BH_*T_*D_], g_kl[BH_*T_*D_];
__device__ __nv_bfloat16 g_vh[BH_*T_*D_], g_vl[BH_*T_*D_];

__device__ __forceinline__ float phi_fn(float x) {
    return (x > 0.f) ? (x + 1.f) : __expf(x);
}

__device__ __forceinline__ void split_store(__nv_bfloat16* dh, __nv_bfloat16* dl,
                                            size_t idx, float v0, float v1) {
    __nv_bfloat16 h0 = __float2bfloat16(v0);
    __nv_bfloat16 h1 = __float2bfloat16(v1);
    __nv_bfloat162 hh; hh.x = h0; hh.y = h1;
    __nv_bfloat162 ll;
    ll.x = __float2bfloat16(v0 - __bfloat162float(h0));
    ll.y = __float2bfloat16(v1 - __bfloat162float(h1));
    *(__nv_bfloat162*)&dh[idx] = hh;
    *(__nv_bfloat162*)&dl[idx] = ll;
}

#define CP_ASYNC16(dst_u32, src_ptr) \
    asm volatile("cp.async.cg.shared.global [%0], [%1], 16;" \
        :: "r"(dst_u32), "l"(src_ptr))
#define CP_COMMIT() asm volatile("cp.async.commit_group;")
#define CP_WAIT1()  asm volatile("cp.async.wait_group 1;")
#define CP_WAIT0()  asm volatile("cp.async.wait_group 0;")

// ---------------------------------------------------------------------------
// Fused split: one launch converts x, wqkv, wproj -> bf16 hi/lo
// ---------------------------------------------------------------------------
#define NX4 (M_*C_/4)
#define NQ4 (C_*3*C_/4)
#define NP4 (C_*C_/4)

__global__ void __launch_bounds__(256)
fused_split_kernel(const float* __restrict__ x,
                   const float* __restrict__ wq,
                   const float* __restrict__ wp)
{
    int i = blockIdx.x * blockDim.x + threadIdx.x;
    const float* src;
    __nv_bfloat16 *hi, *lo;
    int idx;
    if (i < NX4) {
        src = x; hi = g_xhi; lo = g_xlo; idx = i;
    } else if (i < NX4 + NQ4) {
        src = wq; hi = g_wqh; lo = g_wql; idx = i - NX4;
    } else if (i < NX4 + NQ4 + NP4) {
        src = wp; hi = g_wph; lo = g_wpl; idx = i - NX4 - NQ4;
    } else return;

    float4 v = ((const float4*)src)[idx];
    float vv[4] = {v.x, v.y, v.z, v.w};
    __nv_bfloat162 h2[2], l2[2];
#pragma unroll
    for (int p = 0; p < 2; p++) {
        __nv_bfloat16 h0 = __float2bfloat16(vv[p*2]);
        __nv_bfloat16 h1 = __float2bfloat16(vv[p*2+1]);
        h2[p].x = h0; h2[p].y = h1;
        l2[p].x = __float2bfloat16(vv[p*2]   - __bfloat162float(h0));
        l2[p].y = __float2bfloat16(vv[p*2+1] - __bfloat162float(h1));
    }
    ((__nv_bfloat162*)hi)[idx*2]   = h2[0];
    ((__nv_bfloat162*)hi)[idx*2+1] = h2[1];
    ((__nv_bfloat162*)lo)[idx*2]   = l2[0];
    ((__nv_bfloat162*)lo)[idx*2+1] = l2[1];
}

// ---------------------------------------------------------------------------
// QKV GEMM: tile 128x192, 512 threads (16 warps 4x4), warp tile 32x48.
// 3-stage cp.async, 3-term bf16 split. Grid 32x8 = 256 CTAs = one wave.
// SMEM stage: AHI 128x40 (10240), ALO, BHI 32x200 (12800), BLO. stage=46080.
// Cs 128x196 f32 (100352) overlays stages.
// ---------------------------------------------------------------------------
#define Q_LDA 40
#define Q_LDB 200
#define Q_LDC 196
#define Q_AHI 0
#define Q_ALO 10240
#define Q_BHI 20480
#define Q_BPLANE 12800
#define Q_BLO (Q_BHI + Q_BPLANE)
#define Q_STAGE 46080
#define Q_SMEM  (3*Q_STAGE)
#define Q_KT    16
#define Q_BN    192

__global__ void __launch_bounds__(512, 1)
qkv_gemm_192(const __nv_bfloat16* __restrict__ Ahi_g,
             const __nv_bfloat16* __restrict__ Alo_g,
             const __nv_bfloat16* __restrict__ Bhi_g,
             const __nv_bfloat16* __restrict__ Blo_g,
             const float* __restrict__ bias,
             const float* __restrict__ am)
{
    extern __shared__ char smem[];
    float* Cs = (float*)smem;

    const int tid = threadIdx.x;
    const int wid = tid >> 5;
    const int bm = blockIdx.x * 128, bn = blockIdx.y * Q_BN;
    const int wr = wid >> 2, wcol = wid & 3;

    const uint32_t smem_u32 = (uint32_t)__cvta_generic_to_shared(smem);

    // A: 512 uint4/plane; one per thread
    const int ar = tid >> 2, ac = (tid & 3) * 8;
    // B: 768 uint4/plane; id0 = tid, id1 = 512+tid (tid<256)
    const int b1ok = tid < 256;
    const int br0 = tid / 24,        bc0 = (tid % 24) * 8;
    const int br1 = (512 + tid) / 24, bc1 = ((512 + tid) % 24) * 8;

    auto issue_loads = [&](int s, int k0) {
        const uint32_t st = smem_u32 + s * Q_STAGE;
        {
            uint32_t adst = st + Q_AHI + (uint32_t)(ar * Q_LDA + ac) * 2;
            CP_ASYNC16(adst, &Ahi_g[(size_t)(bm + ar) * 512 + k0 + ac]);
            CP_ASYNC16(adst + (Q_ALO - Q_AHI),
                       &Alo_g[(size_t)(bm + ar) * 512 + k0 + ac]);
        }
        {
            uint32_t bdst = st + Q_BHI + (uint32_t)(br0 * Q_LDB + bc0) * 2;
            CP_ASYNC16(bdst, &Bhi_g[(size_t)(k0 + br0) * 1536 + bn + bc0]);
            CP_ASYNC16(bdst + Q_BPLANE, &Blo_g[(size_t)(k0 + br0) * 1536 + bn + bc0]);
        }
        if (b1ok) {
            uint32_t bdst = st + Q_BHI + (uint32_t)(br1 * Q_LDB + bc1) * 2;
            CP_ASYNC16(bdst, &Bhi_g[(size_t)(k0 + br1) * 1536 + bn + bc1]);
            CP_ASYNC16(bdst + Q_BPLANE, &Blo_g[(size_t)(k0 + br1) * 1536 + bn + bc1]);
        }
        CP_COMMIT();
    };

    wmma::fragment<wmma::accumulator, 16, 16, 16, float> acc[2][3];
#pragma unroll
    for (int i = 0; i < 2; i++)
#pragma unroll
        for (int j = 0; j < 3; j++) wmma::fill_fragment(acc[i][j], 0.f);

    issue_loads(0, 0);
    issue_loads(1, 32);

    int cur = 0;
    for (int kt = 0; kt < Q_KT; kt++) {
        if (kt == Q_KT - 1) { CP_WAIT0(); } else { CP_WAIT1(); }
        __syncthreads();

        const char* st = smem + cur * Q_STAGE;
        const __nv_bfloat16* As_hi = (const __nv_bfloat16*)(st + Q_AHI);
        const __nv_bfloat16* As_lo = (const __nv_bfloat16*)(st + Q_ALO);
        const __nv_bfloat16* Bs_hi = (const __nv_bfloat16*)(st + Q_BHI);
        const __nv_bfloat16* Bs_lo = (const __nv_bfloat16*)(st + Q_BLO);

#pragma unroll
        for (int kk = 0; kk < 32; kk += 16) {
            wmma::fragment<wmma::matrix_a, 16, 16, 16, __nv_bfloat16, wmma::row_major> ah[2], al[2];
#pragma unroll
            for (int i = 0; i < 2; i++) {
                wmma::load_matrix_sync(ah[i], &As_hi[(wr * 32 + i * 16) * Q_LDA + kk], Q_LDA);
                wmma::load_matrix_sync(al[i], &As_lo[(wr * 32 + i * 16) * Q_LDA + kk], Q_LDA);
            }
#pragma unroll
            for (int j = 0; j < 3; j++) {
                wmma::fragment<wmma::matrix_b, 16, 16, 16, __nv_bfloat16, wmma::row_major> bh, bl;
                wmma::load_matrix_sync(bh, &Bs_hi[kk * Q_LDB + wcol * 48 + j * 16], Q_LDB);
                wmma::load_matrix_sync(bl, &Bs_lo[kk * Q_LDB + wcol * 48 + j * 16], Q_LDB);
#pragma unroll
                for (int i = 0; i < 2; i++) {
                    wmma::mma_sync(acc[i][j], ah[i], bh, acc[i][j]);
                    wmma::mma_sync(acc[i][j], ah[i], bl, acc[i][j]);
                    wmma::mma_sync(acc[i][j], al[i], bh, acc[i][j]);
                }
            }
        }

        if (kt + 2 < Q_KT) issue_loads((cur + 2) % 3, (kt + 2) * 32);
        cur = (cur + 1) % 3;
    }
    __syncthreads();

    // Single-pass epilogue: Cs 128x196 overlays stages
#pragma unroll
    for (int i = 0; i < 2; i++)
#pragma unroll
        for (int j = 0; j < 3; j++)
            wmma::store_matrix_sync(&Cs[(wr * 32 + i * 16) * Q_LDC + wcol * 48 + j * 16],
                                    acc[i][j], Q_LDC, wmma::mem_row_major);
    __syncthreads();

    {
        const int row = tid >> 2;           // 0..127
        const int cb  = (tid & 3) * 48;     // 0,48,96,144
        const int m = bm + row;
        const int b = m >> 11, t = m & 2047;
        const float maskd = am[((size_t)b * 2048 + t) * 2048 + t];

#pragma unroll
        for (int c8 = 0; c8 < 48; c8 += 8) {
            const int n0 = bn + cb + c8;    // 8-aligned: single section/head
            const int sec = n0 >> 9;
            const int h = (n0 & 511) >> 6;
            __nv_bfloat16 *dh, *dl;
            if (sec == 0)      { dh = g_qh; dl = g_ql; }
            else if (sec == 1) { dh = g_kh; dl = g_kl; }
            else               { dh = g_vh; dl = g_vl; }
            const size_t ob = ((size_t)(b * 8 + h) * 2048 + t) * 64 + (n0 & 63);
            uint32_t hi4[4], lo4[4];
#pragma unroll
            for (int u = 0; u < 8; u += 2) {
                float v0 = Cs[row * Q_LDC + cb + c8 + u]     + bias[n0 + u];
                float v1 = Cs[row * Q_LDC + cb + c8 + u + 1] + bias[n0 + u + 1];
                if (sec == 0)      { v0 = phi_fn(v0);         v1 = phi_fn(v1); }
                else if (sec == 1) { v0 = phi_fn(v0) * maskd; v1 = phi_fn(v1) * maskd; }
                else               { v0 *= maskd;             v1 *= maskd; }
                __nv_bfloat16 h0 = __float2bfloat16(v0);
                __nv_bfloat16 h1 = __float2bfloat16(v1);
                __nv_bfloat162 hh; hh.x = h0; hh.y = h1;
                __nv_bfloat162 ll;
                ll.x = __float2bfloat16(v0 - __bfloat162float(h0));
                ll.y = __float2bfloat16(v1 - __bfloat162float(h1));
                hi4[u >> 1] = *(uint32_t*)&hh;
                lo4[u >> 1] = *(uint32_t*)&ll;
            }
            *(uint4*)&dh[ob] = *(uint4*)hi4;
            *(uint4*)&dl[ob] = *(uint4*)lo4;
        }
    }
}

// ---------------------------------------------------------------------------
// Proj GEMM (R10/R12 config, MODE-1 only): tile 128x128, 256 thr, 3 stages.
// ---------------------------------------------------------------------------
#define G_LDA 40
#define G_LDB 136
#define G_LDC 68
#define G_AHI 0
#define G_ALO 10240
#define G_BHI 20480
#define G_BLO 29184
#define G_STAGE 37888
#define G_SMEM  (3*G_STAGE)
#define G_KT    16

__global__ void __launch_bounds__(256, 2)
proj_gemm_kernel(const __nv_bfloat16* __restrict__ Ahi_g,
                 const __nv_bfloat16* __restrict__ Alo_g,
                 const __nv_bfloat16* __restrict__ Bhi_g,
                 const __nv_bfloat16* __restrict__ Blo_g,
                 const float* __restrict__ bias,
                 float* __restrict__ outp)
{
    constexpr int NW = 512;
    extern __shared__ char smem[];
    float* Cs = (float*)smem;

    const int tid = threadIdx.x;
    const int wid = tid >> 5;
    const int bm = blockIdx.x * 128, bn = blockIdx.y * 128;
    const int wr = wid >> 1, wc = wid & 1;

    const uint32_t smem_u32 = (uint32_t)__cvta_generic_to_shared(smem);

    const int ar[2] = { tid >> 2, (256 + tid) >> 2 };
    const int ac[2] = { (tid & 3) * 8, ((256 + tid) & 3) * 8 };
    const int brr[2] = { tid >> 4, (256 + tid) >> 4 };
    const int bcc[2] = { (tid & 15) * 8, ((256 + tid) & 15) * 8 };

    auto issue_loads = [&](int s, int k0) {
        const uint32_t st = smem_u32 + s * G_STAGE;
#pragma unroll
        for (int q = 0; q < 2; q++) {
            uint32_t adst = st + G_AHI + (uint32_t)(ar[q] * G_LDA + ac[q]) * 2;
            CP_ASYNC16(adst, &Ahi_g[(size_t)(bm + ar[q]) * 512 + k0 + ac[q]]);
            CP_ASYNC16(adst + (G_ALO - G_AHI),
                       &Alo_g[(size_t)(bm + ar[q]) * 512 + k0 + ac[q]]);
            uint32_t bdst = st + G_BHI + (uint32_t)(brr[q] * G_LDB + bcc[q]) * 2;
            CP_ASYNC16(bdst, &Bhi_g[(size_t)(k0 + brr[q]) * NW + bn + bcc[q]]);
            CP_ASYNC16(bdst + (G_BLO - G_BHI),
                       &Blo_g[(size_t)(k0 + brr[q]) * NW + bn + bcc[q]]);
        }
        CP_COMMIT();
    };

    wmma::fragment<wmma::accumulator, 16, 16, 16, float> acc[2][4];
#pragma unroll
    for (int i = 0; i < 2; i++)
#pragma unroll
        for (int j = 0; j < 4; j++) wmma::fill_fragment(acc[i][j], 0.f);

    issue_loads(0, 0);
    issue_loads(1, 32);

    int cur = 0;
    for (int kt = 0; kt < G_KT; kt++) {
        if (kt == G_KT - 1) { CP_WAIT0(); } else { CP_WAIT1(); }
        __syncthreads();

        const char* st = smem + cur * G_STAGE;
        const __nv_bfloat16* As_hi = (const __nv_bfloat16*)(st + G_AHI);
        const __nv_bfloat16* As_lo = (const __nv_bfloat16*)(st + G_ALO);
        const __nv_bfloat16* Bs_hi = (const __nv_bfloat16*)(st + G_BHI);
        const __nv_bfloat16* Bs_lo = (const __nv_bfloat16*)(st + G_BLO);

#pragma unroll
        for (int kk = 0; kk < 32; kk += 16) {
            wmma::fragment<wmma::matrix_a, 16, 16, 16, __nv_bfloat16, wmma::row_major> ah[2], al[2];
            wmma::fragment<wmma::matrix_b, 16, 16, 16, __nv_bfloat16, wmma::row_major> bh[4], bl[4];
#pragma unroll
            for (int i = 0; i < 2; i++) {
                wmma::load_matrix_sync(ah[i], &As_hi[(wr * 32 + i * 16) * G_LDA + kk], G_LDA);
                wmma::load_matrix_sync(al[i], &As_lo[(wr * 32 + i * 16) * G_LDA + kk], G_LDA);
            }
#pragma unroll
            for (int j = 0; j < 4; j++) {
                wmma::load_matrix_sync(bh[j], &Bs_hi[kk * G_LDB + wc * 64 + j * 16], G_LDB);
                wmma::load_matrix_sync(bl[j], &Bs_lo[kk * G_LDB + wc * 64 + j * 16], G_LDB);
            }
#pragma unroll
            for (int i = 0; i < 2; i++)
#pragma unroll
                for (int j = 0; j < 4; j++) {
                    wmma::mma_sync(acc[i][j], ah[i], bh[j], acc[i][j]);
                    wmma::mma_sync(acc[i][j], ah[i], bl[j], acc[i][j]);
                    wmma::mma_sync(acc[i][j], al[i], bh[j], acc[i][j]);
                }
        }

        if (kt + 2 < G_KT) issue_loads((cur + 2) % 3, (kt + 2) * 32);
        cur = (cur + 1) % 3;
    }
    __syncthreads();

#pragma unroll
    for (int p = 0; p < 2; p++) {
        if (wc == p) {
#pragma unroll
            for (int i = 0; i < 2; i++)
#pragma unroll
                for (int j = 0; j < 4; j++)
                    wmma::store_matrix_sync(&Cs[(wr * 32 + i * 16) * G_LDC + j * 16],
                                            acc[i][j], G_LDC, wmma::mem_row_major);
        }
        __syncthreads();

        const int row = tid >> 1;
        const int c0  = (tid & 1) * 32;
        const int m = bm + row;
        const int n0 = bn + p * 64 + c0;
#pragma unroll
        for (int c4 = 0; c4 < 32; c4 += 4) {
            float4 bi = *(const float4*)&bias[n0 + c4];
            float4 o;
            o.x = Cs[row * G_LDC + c0 + c4 + 0] + bi.x;
            o.y = Cs[row * G_LDC + c0 + c4 + 1] + bi.y;
            o.z = Cs[row * G_LDC + c0 + c4 + 2] + bi.z;
            o.w = Cs[row * G_LDC + c0 + c4 + 3] + bi.w;
            *(float4*)&outp[(size_t)m * 512 + n0 + c4] = o;
        }
        __syncthreads();
    }
}

// ---------------------------------------------------------------------------
// Kernel 2: chunk KV sums via HMMA:  S_c = phi_k^T @ v  (64x64, K=128)
// ---------------------------------------------------------------------------
#define CK_KH 0
#define CK_KL 18432
#define CK_VH 36864
#define CK_VL 55296
#define CK_S  73728
#define CK_SMEM 91136

__global__ void __launch_bounds__(256)
chunk_kv_hmma()
{
    extern __shared__ char sm[];
    __nv_bfloat16* kh = (__nv_bfloat16*)(sm + CK_KH);
    __nv_bfloat16* kl = (__nv_bfloat16*)(sm + CK_KL);
    __nv_bfloat16* vh = (__nv_bfloat16*)(sm + CK_VH);
    __nv_bfloat16* vl = (__nv_bfloat16*)(sm + CK_VL);
    float*         Ss = (float*)(sm + CK_S);

    const int tid = threadIdx.x;
    const int wid = tid >> 5;
    const int bh = blockIdx.x >> 4, c = blockIdx.x & 15;
    const int wr = wid >> 1, wc = wid & 1;

    const size_t gb = ((size_t)bh * T_ + c * L_) * 64;

#pragma unroll
    for (int q = 0; q < 4; q++) {
        int f = q * 256 + tid;
        int r = f >> 3, c8 = (f & 7) * 8;
        int so = r * 72 + c8;
        *(uint4*)&kh[so] = *(const uint4*)&g_kh[gb + (size_t)f * 8];
        *(uint4*)&kl[so] = *(const uint4*)&g_kl[gb + (size_t)f * 8];
        *(uint4*)&vh[so] = *(const uint4*)&g_vh[gb + (size_t)f * 8];
        *(uint4*)&vl[so] = *(const uint4*)&g_vl[gb + (size_t)f * 8];
    }
    __syncthreads();

    wmma::fragment<wmma::accumulator, 16, 16, 16, float> acc[2];
    wmma::fill_fragment(acc[0], 0.f);
    wmma::fill_fragment(acc[1], 0.f);

#pragma unroll
    for (int kk = 0; kk < 128; kk += 16) {
        wmma::fragment<wmma::matrix_a, 16, 16, 16, __nv_bfloat16, wmma::col_major> aH, aL;
        wmma::load_matrix_sync(aH, &kh[kk * 72 + wr * 16], 72);
        wmma::load_matrix_sync(aL, &kl[kk * 72 + wr * 16], 72);
#pragma unroll
        for (int j = 0; j < 2; j++) {
            wmma::fragment<wmma::matrix_b, 16, 16, 16, __nv_bfloat16, wmma::row_major> bH, bL;
            wmma::load_matrix_sync(bH, &vh[kk * 72 + wc * 32 + j * 16], 72);
            wmma::load_matrix_sync(bL, &vl[kk * 72 + wc * 32 + j * 16], 72);
            wmma::mma_sync(acc[j], aH, bH, acc[j]);
            wmma::mma_sync(acc[j], aH, bL, acc[j]);
            wmma::mma_sync(acc[j], aL, bH, acc[j]);
        }
    }
#pragma unroll
    for (int j = 0; j < 2; j++)
        wmma::store_matrix_sync(&Ss[(wr * 16) * 68 + wc * 32 + j * 16], acc[j],
                                68, wmma::mem_row_major);

    float ks = 0.f;
    if (tid < 64) {
        for (int t = 0; t < 128; t++)
            ks += __bfloat162float(kh[t * 72 + tid]) + __bfloat162float(kl[t * 72 + tid]);
    }
    __syncthreads();

    const size_t ob = (size_t)(bh * NC_ + c) * 4096;
    for (int e = tid; e < 4096; e += 256) {
        int i = e >> 6, j = e & 63;
        g_kv[ob + e] = Ss[i * 68 + j];
    }
    if (tid < 64)
        g_ks[(size_t)(bh * NC_ + c) * 64 + tid] = ks;
}

// ---------------------------------------------------------------------------
// Kernel 3: register-batched exclusive prefix scan.
// ---------------------------------------------------------------------------
__global__ void __launch_bounds__(256, 4)
chunk_scan_fast()
{
    const int tid = threadIdx.x;
    const int q  = blockIdx.x;
    const int bh = blockIdx.y;

    if (q < 16) {
        float v[NC_];
        const size_t base = (size_t)bh * NC_ * 4096 + q * 256 + tid;
#pragma unroll
        for (int c = 0; c < NC_; c++)
            v[c] = g_kv[base + (size_t)c * 4096];
        float run = 0.f;
#pragma unroll
        for (int c = 0; c < NC_; c++) {
            float tmp = v[c];
            v[c] = run;
            run += tmp;
        }
#pragma unroll
        for (int c = 0; c < NC_; c++)
            g_kv[base + (size_t)c * 4096] = v[c];
    } else if (tid < 64) {
        float v[NC_];
        const size_t base = (size_t)bh * NC_ * 64 + tid;
#pragma unroll
        for (int c = 0; c < NC_; c++)
            v[c] = g_ks[base + (size_t)c * 64];
        float run = 0.f;
#pragma unroll
        for (int c = 0; c < NC_; c++) {
            float tmp = v[c];
            v[c] = run;
            run += tmp;
        }
#pragma unroll
        for (int c = 0; c < NC_; c++)
            g_ks[base + (size_t)c * 64] = v[c];
    }
}

// ---------------------------------------------------------------------------
// Kernel 4: attention chunk, full HMMA (R10 winner, unchanged)
// ---------------------------------------------------------------------------
#define AQ_H 0
#define AQ_L 18432
#define AK_H 36864
#define AK_L 55296
#define AVH_ 73728
#define AVL_ 92160
#define AS_H 110592
#define AS_L 119808
#define AA_  129024
#define ADEN2 198656
#define ADEN  199680
#define AKP   200192
#define ATT_SMEM 200448
#define A_HI_OFF 0
#define A_LO_OFF 34816

__global__ void __launch_bounds__(256)
attn_hmma_kernel()
{
    extern __shared__ char sm[];
    __nv_bfloat16* qh = (__nv_bfloat16*)(sm + AQ_H);
    __nv_bfloat16* ql = (__nv_bfloat16*)(sm + AQ_L);
    __nv_bfloat16* kh = (__nv_bfloat16*)(sm + AK_H);
    __nv_bfloat16* kl = (__nv_bfloat16*)(sm + AK_L);
    __nv_bfloat16* vh = (__nv_bfloat16*)(sm + AVH_);
    __nv_bfloat16* vl = (__nv_bfloat16*)(sm + AVL_);
    __nv_bfloat16* Sh = (__nv_bfloat16*)(sm + AS_H);
    __nv_bfloat16* Sl = (__nv_bfloat16*)(sm + AS_L);
    float* Afp  = (float*)(sm + AA_);
    float* Yst  = (float*)(sm + AA_);
    float* den2 = (float*)(sm + ADEN2);
    float* den  = (float*)(sm + ADEN);
    float* kp   = (float*)(sm + AKP);
    __nv_bfloat16* Ahi = (__nv_bfloat16*)(sm + A_HI_OFF);
    __nv_bfloat16* Alo = (__nv_bfloat16*)(sm + A_LO_OFF);

    const int tid = threadIdx.x;
    const int wid = tid >> 5;
    const int bh = blockIdx.x >> 4, c = blockIdx.x & 15;
    const int wr = wid >> 1, wc = wid & 1;

    const size_t gb = ((size_t)bh * T_ + c * L_) * 64;

#pragma unroll
    for (int q = 0; q < 4; q++) {
        int f = q * 256 + tid;
        int r = f >> 3, c8 = (f & 7) * 8;
        int so = r * 72 + c8;
        *(uint4*)&qh[so] = *(const uint4*)&g_qh[gb + (size_t)f * 8];
        *(uint4*)&ql[so] = *(const uint4*)&g_ql[gb + (size_t)f * 8];
        *(uint4*)&kh[so] = *(const uint4*)&g_kh[gb + (size_t)f * 8];
        *(uint4*)&kl[so] = *(const uint4*)&g_kl[gb + (size_t)f * 8];
        *(uint4*)&vh[so] = *(const uint4*)&g_vh[gb + (size_t)f * 8];
        *(uint4*)&vl[so] = *(const uint4*)&g_vl[gb + (size_t)f * 8];
    }
    {
        size_t sb = (size_t)(bh * NC_ + c) * 4096;
        for (int e = tid; e < 4096; e += 256) {
            int i = e >> 6, j = e & 63;
            float v = g_kv[sb + e];
            __nv_bfloat16 h = __float2bfloat16(v);
            Sh[i * 72 + j] = h;
            Sl[i * 72 + j] = __float2bfloat16(v - __bfloat162float(h));
        }
        if (tid < 64) kp[tid] = g_ks[(size_t)(bh * NC_ + c) * 64 + tid];
    }
    __syncthreads();

    wmma::fragment<wmma::accumulator, 16, 16, 16, float> nAcc[2][2];
#pragma unroll
    for (int i = 0; i < 2; i++)
#pragma unroll
        for (int j = 0; j < 2; j++) wmma::fill_fragment(nAcc[i][j], 0.f);

#pragma unroll
    for (int kk = 0; kk < 64; kk += 16) {
        wmma::fragment<wmma::matrix_a, 16, 16, 16, __nv_bfloat16, wmma::row_major> aH[2], aL[2];
#pragma unroll
        for (int i = 0; i < 2; i++) {
            wmma::load_matrix_sync(aH[i], &qh[(wr * 32 + i * 16) * 72 + kk], 72);
            wmma::load_matrix_sync(aL[i], &ql[(wr * 32 + i * 16) * 72 + kk], 72);
        }
#pragma unroll
        for (int j = 0; j < 2; j++) {
            wmma::fragment<wmma::matrix_b, 16, 16, 16, __nv_bfloat16, wmma::row_major> bH, bL;
            wmma::load_matrix_sync(bH, &Sh[kk * 72 + wc * 32 + j * 16], 72);
            wmma::load_matrix_sync(bL, &Sl[kk * 72 + wc * 32 + j * 16], 72);
#pragma unroll
            for (int i = 0; i < 2; i++) {
                wmma::mma_sync(nAcc[i][j], aH[i], bH, nAcc[i][j]);
                wmma::mma_sync(nAcc[i][j], aH[i], bL, nAcc[i][j]);
                wmma::mma_sync(nAcc[i][j], aL[i], bH, nAcc[i][j]);
            }
        }
    }

    {
        wmma::fragment<wmma::accumulator, 16, 16, 16, float> aAcc[2][4];
#pragma unroll
        for (int i = 0; i < 2; i++)
#pragma unroll
            for (int j = 0; j < 4; j++) wmma::fill_fragment(aAcc[i][j], 0.f);

#pragma unroll
        for (int kk = 0; kk < 64; kk += 16) {
            wmma::fragment<wmma::matrix_a, 16, 16, 16, __nv_bfloat16, wmma::row_major> aH[2], aL[2];
#pragma unroll
            for (int i = 0; i < 2; i++) {
                wmma::load_matrix_sync(aH[i], &qh[(wr * 32 + i * 16) * 72 + kk], 72);
                wmma::load_matrix_sync(aL[i], &ql[(wr * 32 + i * 16) * 72 + kk], 72);
            }
#pragma unroll
            for (int j = 0; j < 4; j++) {
                wmma::fragment<wmma::matrix_b, 16, 16, 16, __nv_bfloat16, wmma::col_major> bH, bL;
                wmma::load_matrix_sync(bH, &kh[(wc * 64 + j * 16) * 72 + kk], 72);
                wmma::load_matrix_sync(bL, &kl[(wc * 64 + j * 16) * 72 + kk], 72);
#pragma unroll
                for (int i = 0; i < 2; i++) {
                    wmma::mma_sync(aAcc[i][j], aH[i], bH, aAcc[i][j]);
                    wmma::mma_sync(aAcc[i][j], aH[i], bL, aAcc[i][j]);
                    wmma::mma_sync(aAcc[i][j], aL[i], bH, aAcc[i][j]);
                }
            }
        }
#pragma unroll
        for (int i = 0; i < 2; i++)
#pragma unroll
            for (int j = 0; j < 4; j++)
                wmma::store_matrix_sync(&Afp[(wr * 32 + i * 16) * 136 + wc * 64 + j * 16],
                                        aAcc[i][j], 136, wmma::mem_row_major);
    }
    __syncthreads();

    {
        int t = tid >> 1, hf = tid & 1;
        float s = 0.f;
        for (int s2 = 0; s2 < 64; s2++) {
            int sg = hf * 64 + s2;
            if (sg <= t) s += Afp[t * 136 + sg];
        }
        den2[tid] = s;
    }
    __syncthreads();
    if (tid < 128) {
        float s = den2[tid * 2] + den2[tid * 2 + 1];
        for (int d = 0; d < 64; d++)
            s += (__bfloat162float(qh[tid * 72 + d]) +
                  __bfloat162float(ql[tid * 72 + d])) * kp[d];
        den[tid] = fmaxf(s, EPS_);
    }
    __syncthreads();
    for (int e = tid; e < 128 * 128; e += 256) {
        int t = e >> 7, s = e & 127;
        float v = (s <= t) ? Afp[t * 136 + s] : 0.f;
        __nv_bfloat16 h = __float2bfloat16(v);
        Ahi[t * 136 + s] = h;
        Alo[t * 136 + s] = __float2bfloat16(v - __bfloat162float(h));
    }
    __syncthreads();

#pragma unroll
    for (int kk = 0; kk < 128; kk += 16) {
        wmma::fragment<wmma::matrix_a, 16, 16, 16, __nv_bfloat16, wmma::row_major> aH[2], aL[2];
#pragma unroll
        for (int i = 0; i < 2; i++) {
            wmma::load_matrix_sync(aH[i], &Ahi[(wr * 32 + i * 16) * 136 + kk], 136);
            wmma::load_matrix_sync(aL[i], &Alo[(wr * 32 + i * 16) * 136 + kk], 136);
        }
#pragma unroll
        for (int j = 0; j < 2; j++) {
            wmma::fragment<wmma::matrix_b, 16, 16, 16, __nv_bfloat16, wmma::row_major> bH, bL;
            wmma::load_matrix_sync(bH, &vh[kk * 72 + wc * 32 + j * 16], 72);
            wmma::load_matrix_sync(bL, &vl[kk * 72 + wc * 32 + j * 16], 72);
#pragma unroll
            for (int i = 0; i < 2; i++) {
                wmma::mma_sync(nAcc[i][j], aH[i], bH, nAcc[i][j]);
                wmma::mma_sync(nAcc[i][j], aH[i], bL, nAcc[i][j]);
                wmma::mma_sync(nAcc[i][j], aL[i], bH, nAcc[i][j]);
            }
        }
    }
    __syncthreads();
#pragma unroll
    for (int i = 0; i < 2; i++)
#pragma unroll
        for (int j = 0; j < 2; j++)
            wmma::store_matrix_sync(&Yst[(wr * 32 + i * 16) * 68 + wc * 32 + j * 16],
                                    nAcc[i][j], 68, wmma::mem_row_major);
    __syncthreads();

    {
        const int bidx = bh >> 3, h = bh & 7;
        int t = tid >> 1, hf = tid & 1;
        float inv = 1.f / den[t];
        int tg = c * L_ + t;
        size_t yb = ((size_t)bidx * T_ + tg) * C_ + h * 64 + hf * 32;
        for (int c2 = 0; c2 < 32; c2 += 2) {
            float v0 = Yst[t * 68 + hf * 32 + c2]     * inv;
            float v1 = Yst[t * 68 + hf * 32 + c2 + 1] * inv;
            split_store(g_yhi, g_ylo, yb + c2, v0, v1);
        }
    }
}

// ---------------------------------------------------------------------------
extern "C" void kernel_launch(void* const* d_in, const int* in_sizes, int n_in,
                              void* d_out, int out_size)
{
    const float* x     = (const float*)d_in[0];
    const float* am    = (const float*)d_in[1];
    const float* wqkv  = (const float*)d_in[2];
    const float* bqkv  = (const float*)d_in[3];
    const float* wproj = (const float*)d_in[4];
    const float* bproj = (const float*)d_in[5];
    float* out = (float*)d_out;

    static bool attr_set = false;
    if (!attr_set) {
        cudaFuncSetAttribute(qkv_gemm_192,
                             cudaFuncAttributeMaxDynamicSharedMemorySize, Q_SMEM);
        cudaFuncSetAttribute(proj_gemm_kernel,
                             cudaFuncAttributeMaxDynamicSharedMemorySize, G_SMEM);
        cudaFuncSetAttribute(chunk_kv_hmma,
                             cudaFuncAttributeMaxDynamicSharedMemorySize, CK_SMEM);
        cudaFuncSetAttribute(attn_hmma_kernel,
                             cudaFuncAttributeMaxDynamicSharedMemorySize, ATT_SMEM);
        attr_set = true;
    }

    __nv_bfloat16 *xhi, *xlo, *wqh, *wql, *wph, *wpl, *yhi, *ylo;
    cudaGetSymbolAddress((void**)&xhi, g_xhi);
    cudaGetSymbolAddress((void**)&xlo, g_xlo);
    cudaGetSymbolAddress((void**)&wqh, g_wqh);
    cudaGetSymbolAddress((void**)&wql, g_wql);
    cudaGetSymbolAddress((void**)&wph, g_wph);
    cudaGetSymbolAddress((void**)&wpl, g_wpl);
    cudaGetSymbolAddress((void**)&yhi, g_yhi);
    cudaGetSymbolAddress((void**)&ylo, g_ylo);

    const int nsplit4 = NX4 + NQ4 + NP4;
    fused_split_kernel<<<(nsplit4 + 255) / 256, 256>>>(x, wqkv, wproj);

    dim3 g1(M_ / 128, 1536 / Q_BN);
    qkv_gemm_192<<<g1, 512, Q_SMEM>>>(xhi, xlo, wqh, wql, bqkv, am);

    chunk_kv_hmma<<<BH_ * NC_, 256, CK_SMEM>>>();

    dim3 gs(17, BH_);
    chunk_scan_fast<<<gs, 256>>>();

    attn_hmma_kernel<<<BH_ * NC_, 256, ATT_SMEM>>>();

    dim3 g5(M_ / 128, 512 / 128);
    proj_gemm_kernel<<<g5, 256, G_SMEM>>>(yhi, ylo, wph, wpl, bproj, out);
}

// round 14
// speedup vs baseline: 1.0471x; 1.0471x over previous
#include <cuda_runtime.h>
#include <cuda_bf16.h>
#include <mma.h>
#include <cstdint>
#include <math.h>

using namespace nvcuda;

#define B_   2
#define T_   2048
#define C_   512
#define H_   8
#define D_   64
#define BH_  (B_*H_)
#define L_   128
#define NC_  (T_/L_)
#define M_   (B_*T_)
#define EPS_ 1e-8f

// Scratch (device globals)
__device__ float g_kv  [BH_*NC_*D_*D_];
__device__ float g_ks  [BH_*NC_*D_];

// bf16 hi/lo split buffers
__device__ __nv_bfloat16 g_xhi[M_*C_],  g_xlo[M_*C_];
__device__ __nv_bfloat16 g_wqh[C_*3*C_], g_wql[C_*3*C_];
__device__ __nv_bfloat16 g_wph[C_*C_],  g_wpl[C_*C_];
__device__ __nv_bfloat16 g_yhi[M_*C_],  g_ylo[M_*C_];
__device__ __nv_bfloat16 g_qh[BH_*T_*D_], g_ql[BH_*T_*D_];
__device__ __nv_bfloat16 g_kh[BH_*T_*D_], g_kl[BH_*T_*D_];
__device__ __nv_bfloat16 g_vh[BH_*T_*D_], g_vl[BH_*T_*D_];

__device__ __forceinline__ float phi_fn(float x) {
    return (x > 0.f) ? (x + 1.f) : __expf(x);
}

__device__ __forceinline__ void split_store(__nv_bfloat16* dh, __nv_bfloat16* dl,
                                            size_t idx, float v0, float v1) {
    __nv_bfloat16 h0 = __float2bfloat16(v0);
    __nv_bfloat16 h1 = __float2bfloat16(v1);
    __nv_bfloat162 hh; hh.x = h0; hh.y = h1;
    __nv_bfloat162 ll;
    ll.x = __float2bfloat16(v0 - __bfloat162float(h0));
    ll.y = __float2bfloat16(v1 - __bfloat162float(h1));
    *(__nv_bfloat162*)&dh[idx] = hh;
    *(__nv_bfloat162*)&dl[idx] = ll;
}

#define CP_ASYNC16(dst_u32, src_ptr) \
    asm volatile("cp.async.cg.shared.global [%0], [%1], 16;" \
        :: "r"(dst_u32), "l"(src_ptr))
#define CP_COMMIT() asm volatile("cp.async.commit_group;")
#define CP_WAIT1()  asm volatile("cp.async.wait_group 1;")
#define CP_WAIT0()  asm volatile("cp.async.wait_group 0;")

// ---------------------------------------------------------------------------
// Fused split: one launch converts x, wqkv, wproj -> bf16 hi/lo
// ---------------------------------------------------------------------------
#define NX4 (M_*C_/4)
#define NQ4 (C_*3*C_/4)
#define NP4 (C_*C_/4)

__global__ void __launch_bounds__(256)
fused_split_kernel(const float* __restrict__ x,
                   const float* __restrict__ wq,
                   const float* __restrict__ wp)
{
    int i = blockIdx.x * blockDim.x + threadIdx.x;
    const float* src;
    __nv_bfloat16 *hi, *lo;
    int idx;
    if (i < NX4) {
        src = x; hi = g_xhi; lo = g_xlo; idx = i;
    } else if (i < NX4 + NQ4) {
        src = wq; hi = g_wqh; lo = g_wql; idx = i - NX4;
    } else if (i < NX4 + NQ4 + NP4) {
        src = wp; hi = g_wph; lo = g_wpl; idx = i - NX4 - NQ4;
    } else return;

    float4 v = ((const float4*)src)[idx];
    float vv[4] = {v.x, v.y, v.z, v.w};
    __nv_bfloat162 h2[2], l2[2];
#pragma unroll
    for (int p = 0; p < 2; p++) {
        __nv_bfloat16 h0 = __float2bfloat16(vv[p*2]);
        __nv_bfloat16 h1 = __float2bfloat16(vv[p*2+1]);
        h2[p].x = h0; h2[p].y = h1;
        l2[p].x = __float2bfloat16(vv[p*2]   - __bfloat162float(h0));
        l2[p].y = __float2bfloat16(vv[p*2+1] - __bfloat162float(h1));
    }
    ((__nv_bfloat162*)hi)[idx*2]   = h2[0];
    ((__nv_bfloat162*)hi)[idx*2+1] = h2[1];
    ((__nv_bfloat162*)lo)[idx*2]   = l2[0];
    ((__nv_bfloat162*)lo)[idx*2+1] = l2[1];
}

// ---------------------------------------------------------------------------
// 3-stage cp.async pipelined wmma bf16 GEMM (R12 config, tile 128x128).
// MODE 0: QKV, MODE 1: proj
// ---------------------------------------------------------------------------
#define G_LDA 40
#define G_LDB 136
#define G_LDC 68
#define G_AHI 0
#define G_ALO 10240
#define G_BHI 20480
#define G_BLO 29184
#define G_STAGE 37888
#define G_SMEM  (3*G_STAGE)
#define G_KT    16

template<int MODE>
__global__ void __launch_bounds__(256, 2)
wmma_gemm_kernel(const __nv_bfloat16* __restrict__ Ahi_g,
                 const __nv_bfloat16* __restrict__ Alo_g,
                 const __nv_bfloat16* __restrict__ Bhi_g,
                 const __nv_bfloat16* __restrict__ Blo_g,
                 const float* __restrict__ bias,
                 const float* __restrict__ am,
                 float* __restrict__ outp)
{
    constexpr int NW = (MODE == 0) ? 1536 : 512;
    extern __shared__ char smem[];
    float* Cs = (float*)smem;

    const int tid = threadIdx.x;
    const int wid = tid >> 5;
    const int bm = blockIdx.x * 128, bn = blockIdx.y * 128;
    const int wr = wid >> 1, wc = wid & 1;

    const uint32_t smem_u32 = (uint32_t)__cvta_generic_to_shared(smem);

    const int ar[2] = { tid >> 2, (256 + tid) >> 2 };
    const int ac[2] = { (tid & 3) * 8, ((256 + tid) & 3) * 8 };
    const int brr[2] = { tid >> 4, (256 + tid) >> 4 };
    const int bcc[2] = { (tid & 15) * 8, ((256 + tid) & 15) * 8 };

    auto issue_loads = [&](int s, int k0) {
        const uint32_t st = smem_u32 + s * G_STAGE;
#pragma unroll
        for (int q = 0; q < 2; q++) {
            uint32_t adst = st + G_AHI + (uint32_t)(ar[q] * G_LDA + ac[q]) * 2;
            CP_ASYNC16(adst, &Ahi_g[(size_t)(bm + ar[q]) * 512 + k0 + ac[q]]);
            CP_ASYNC16(adst + (G_ALO - G_AHI),
                       &Alo_g[(size_t)(bm + ar[q]) * 512 + k0 + ac[q]]);
            uint32_t bdst = st + G_BHI + (uint32_t)(brr[q] * G_LDB + bcc[q]) * 2;
            CP_ASYNC16(bdst, &Bhi_g[(size_t)(k0 + brr[q]) * NW + bn + bcc[q]]);
            CP_ASYNC16(bdst + (G_BLO - G_BHI),
                       &Blo_g[(size_t)(k0 + brr[q]) * NW + bn + bcc[q]]);
        }
        CP_COMMIT();
    };

    wmma::fragment<wmma::accumulator, 16, 16, 16, float> acc[2][4];
#pragma unroll
    for (int i = 0; i < 2; i++)
#pragma unroll
        for (int j = 0; j < 4; j++) wmma::fill_fragment(acc[i][j], 0.f);

    issue_loads(0, 0);
    issue_loads(1, 32);

    int cur = 0;
    for (int kt = 0; kt < G_KT; kt++) {
        if (kt == G_KT - 1) { CP_WAIT0(); } else { CP_WAIT1(); }
        __syncthreads();

        const char* st = smem + cur * G_STAGE;
        const __nv_bfloat16* As_hi = (const __nv_bfloat16*)(st + G_AHI);
        const __nv_bfloat16* As_lo = (const __nv_bfloat16*)(st + G_ALO);
        const __nv_bfloat16* Bs_hi = (const __nv_bfloat16*)(st + G_BHI);
        const __nv_bfloat16* Bs_lo = (const __nv_bfloat16*)(st + G_BLO);

#pragma unroll
        for (int kk = 0; kk < 32; kk += 16) {
            wmma::fragment<wmma::matrix_a, 16, 16, 16, __nv_bfloat16, wmma::row_major> ah[2], al[2];
            wmma::fragment<wmma::matrix_b, 16, 16, 16, __nv_bfloat16, wmma::row_major> bh[4], bl[4];
#pragma unroll
            for (int i = 0; i < 2; i++) {
                wmma::load_matrix_sync(ah[i], &As_hi[(wr * 32 + i * 16) * G_LDA + kk], G_LDA);
                wmma::load_matrix_sync(al[i], &As_lo[(wr * 32 + i * 16) * G_LDA + kk], G_LDA);
            }
#pragma unroll
            for (int j = 0; j < 4; j++) {
                wmma::load_matrix_sync(bh[j], &Bs_hi[kk * G_LDB + wc * 64 + j * 16], G_LDB);
                wmma::load_matrix_sync(bl[j], &Bs_lo[kk * G_LDB + wc * 64 + j * 16], G_LDB);
            }
#pragma unroll
            for (int i = 0; i < 2; i++)
#pragma unroll
                for (int j = 0; j < 4; j++) {
                    wmma::mma_sync(acc[i][j], ah[i], bh[j], acc[i][j]);
                    wmma::mma_sync(acc[i][j], ah[i], bl[j], acc[i][j]);
                    wmma::mma_sync(acc[i][j], al[i], bh[j], acc[i][j]);
                }
        }

        if (kt + 2 < G_KT) issue_loads((cur + 2) % 3, (kt + 2) * 32);
        cur = (cur + 1) % 3;
    }
    __syncthreads();

#pragma unroll
    for (int p = 0; p < 2; p++) {
        if (wc == p) {
#pragma unroll
            for (int i = 0; i < 2; i++)
#pragma unroll
                for (int j = 0; j < 4; j++)
                    wmma::store_matrix_sync(&Cs[(wr * 32 + i * 16) * G_LDC + j * 16],
                                            acc[i][j], G_LDC, wmma::mem_row_major);
        }
        __syncthreads();

        const int row = tid >> 1;
        const int c0  = (tid & 1) * 32;
        const int m = bm + row;
        const int n0 = bn + p * 64 + c0;

        if (MODE == 0) {
            const int b = m >> 11, t = m & 2047;
            const float maskd = am[((size_t)b * 2048 + t) * 2048 + t];
            const int sec = n0 >> 9;
            const int h = (n0 & 511) >> 6;
            __nv_bfloat16 *dh, *dl;
            if (sec == 0)      { dh = g_qh; dl = g_ql; }
            else if (sec == 1) { dh = g_kh; dl = g_kl; }
            else               { dh = g_vh; dl = g_vl; }
            const size_t ob = ((size_t)(b * 8 + h) * 2048 + t) * 64 + (n0 & 63);
#pragma unroll
            for (int c8 = 0; c8 < 32; c8 += 8) {
                uint32_t hi4[4], lo4[4];
#pragma unroll
                for (int u = 0; u < 8; u += 2) {
                    float v0 = Cs[row * G_LDC + c0 + c8 + u]     + bias[n0 + c8 + u];
                    float v1 = Cs[row * G_LDC + c0 + c8 + u + 1] + bias[n0 + c8 + u + 1];
                    if (sec == 0)      { v0 = phi_fn(v0);         v1 = phi_fn(v1); }
                    else if (sec == 1) { v0 = phi_fn(v0) * maskd; v1 = phi_fn(v1) * maskd; }
                    else               { v0 *= maskd;             v1 *= maskd; }
                    __nv_bfloat16 h0 = __float2bfloat16(v0);
                    __nv_bfloat16 h1 = __float2bfloat16(v1);
                    __nv_bfloat162 hh; hh.x = h0; hh.y = h1;
                    __nv_bfloat162 ll;
                    ll.x = __float2bfloat16(v0 - __bfloat162float(h0));
                    ll.y = __float2bfloat16(v1 - __bfloat162float(h1));
                    hi4[u >> 1] = *(uint32_t*)&hh;
                    lo4[u >> 1] = *(uint32_t*)&ll;
                }
                *(uint4*)&dh[ob + c8] = *(uint4*)hi4;
                *(uint4*)&dl[ob + c8] = *(uint4*)lo4;
            }
        } else {
#pragma unroll
            for (int c4 = 0; c4 < 32; c4 += 4) {
                float4 bi = *(const float4*)&bias[n0 + c4];
                float4 o;
                o.x = Cs[row * G_LDC + c0 + c4 + 0] + bi.x;
                o.y = Cs[row * G_LDC + c0 + c4 + 1] + bi.y;
                o.z = Cs[row * G_LDC + c0 + c4 + 2] + bi.z;
                o.w = Cs[row * G_LDC + c0 + c4 + 3] + bi.w;
                *(float4*)&outp[(size_t)m * 512 + n0 + c4] = o;
            }
        }
        __syncthreads();
    }
}

// ---------------------------------------------------------------------------
// Kernel 2: chunk KV sums via HMMA; ks-sum parallelized (4 groups x 64 cols)
// ---------------------------------------------------------------------------
#define CK_KH 0
#define CK_KL 18432
#define CK_VH 36864
#define CK_VL 55296
#define CK_S  73728
#define CK_KS (CK_S + 64*68*4)
#define CK_SMEM (CK_KS + 256*4)

__global__ void __launch_bounds__(256)
chunk_kv_hmma()
{
    extern __shared__ char sm[];
    __nv_bfloat16* kh = (__nv_bfloat16*)(sm + CK_KH);
    __nv_bfloat16* kl = (__nv_bfloat16*)(sm + CK_KL);
    __nv_bfloat16* vh = (__nv_bfloat16*)(sm + CK_VH);
    __nv_bfloat16* vl = (__nv_bfloat16*)(sm + CK_VL);
    float*         Ss = (float*)(sm + CK_S);
    float*         kss = (float*)(sm + CK_KS);

    const int tid = threadIdx.x;
    const int wid = tid >> 5;
    const int bh = blockIdx.x >> 4, c = blockIdx.x & 15;
    const int wr = wid >> 1, wc = wid & 1;

    const size_t gb = ((size_t)bh * T_ + c * L_) * 64;

#pragma unroll
    for (int q = 0; q < 4; q++) {
        int f = q * 256 + tid;
        int r = f >> 3, c8 = (f & 7) * 8;
        int so = r * 72 + c8;
        *(uint4*)&kh[so] = *(const uint4*)&g_kh[gb + (size_t)f * 8];
        *(uint4*)&kl[so] = *(const uint4*)&g_kl[gb + (size_t)f * 8];
        *(uint4*)&vh[so] = *(const uint4*)&g_vh[gb + (size_t)f * 8];
        *(uint4*)&vl[so] = *(const uint4*)&g_vl[gb + (size_t)f * 8];
    }
    __syncthreads();

    wmma::fragment<wmma::accumulator, 16, 16, 16, float> acc[2];
    wmma::fill_fragment(acc[0], 0.f);
    wmma::fill_fragment(acc[1], 0.f);

#pragma unroll
    for (int kk = 0; kk < 128; kk += 16) {
        wmma::fragment<wmma::matrix_a, 16, 16, 16, __nv_bfloat16, wmma::col_major> aH, aL;
        wmma::load_matrix_sync(aH, &kh[kk * 72 + wr * 16], 72);
        wmma::load_matrix_sync(aL, &kl[kk * 72 + wr * 16], 72);
#pragma unroll
        for (int j = 0; j < 2; j++) {
            wmma::fragment<wmma::matrix_b, 16, 16, 16, __nv_bfloat16, wmma::row_major> bH, bL;
            wmma::load_matrix_sync(bH, &vh[kk * 72 + wc * 32 + j * 16], 72);
            wmma::load_matrix_sync(bL, &vl[kk * 72 + wc * 32 + j * 16], 72);
            wmma::mma_sync(acc[j], aH, bH, acc[j]);
            wmma::mma_sync(acc[j], aH, bL, acc[j]);
            wmma::mma_sync(acc[j], aL, bH, acc[j]);
        }
    }
#pragma unroll
    for (int j = 0; j < 2; j++)
        wmma::store_matrix_sync(&Ss[(wr * 16) * 68 + wc * 32 + j * 16], acc[j],
                                68, wmma::mem_row_major);

    // parallel ks: group g sums rows [g*32, g*32+32) for column col
    {
        const int col = tid & 63, g = tid >> 6;
        float s = 0.f;
        for (int t = g * 32; t < g * 32 + 32; t++)
            s += __bfloat162float(kh[t * 72 + col]) + __bfloat162float(kl[t * 72 + col]);
        kss[tid] = s;
    }
    __syncthreads();

    const size_t ob = (size_t)(bh * NC_ + c) * 4096;
    for (int e = tid; e < 4096; e += 256) {
        int i = e >> 6, j = e & 63;
        g_kv[ob + e] = Ss[i * 68 + j];
    }
    if (tid < 64)
        g_ks[(size_t)(bh * NC_ + c) * 64 + tid] =
            kss[tid] + kss[64 + tid] + kss[128 + tid] + kss[192 + tid];
}

// ---------------------------------------------------------------------------
// Kernel 3: register-batched exclusive prefix scan (R12)
// ---------------------------------------------------------------------------
__global__ void __launch_bounds__(256, 4)
chunk_scan_fast()
{
    const int tid = threadIdx.x;
    const int q  = blockIdx.x;
    const int bh = blockIdx.y;

    if (q < 16) {
        float v[NC_];
        const size_t base = (size_t)bh * NC_ * 4096 + q * 256 + tid;
#pragma unroll
        for (int c = 0; c < NC_; c++)
            v[c] = g_kv[base + (size_t)c * 4096];
        float run = 0.f;
#pragma unroll
        for (int c = 0; c < NC_; c++) {
            float tmp = v[c];
            v[c] = run;
            run += tmp;
        }
#pragma unroll
        for (int c = 0; c < NC_; c++)
            g_kv[base + (size_t)c * 4096] = v[c];
    } else if (tid < 64) {
        float v[NC_];
        const size_t base = (size_t)bh * NC_ * 64 + tid;
#pragma unroll
        for (int c = 0; c < NC_; c++)
            v[c] = g_ks[base + (size_t)c * 64];
        float run = 0.f;
#pragma unroll
        for (int c = 0; c < NC_; c++) {
            float tmp = v[c];
            v[c] = run;
            run += tmp;
        }
#pragma unroll
        for (int c = 0; c < NC_; c++)
            g_ks[base + (size_t)c * 64] = v[c];
    }
}

// ---------------------------------------------------------------------------
// Kernel 4: attention chunk, full HMMA, 512 threads (16 warps 4x4)
// ---------------------------------------------------------------------------
#define AQ_H 0
#define AQ_L 18432
#define AK_H 36864
#define AK_L 55296
#define AVH_ 73728
#define AVL_ 92160
#define AS_H 110592
#define AS_L 119808
#define AA_  129024
#define ADEN2 198656
#define ADEN  200704
#define AKP   201216
#define ATT_SMEM 201472
#define A_HI_OFF 0
#define A_LO_OFF 34816

__global__ void __launch_bounds__(512, 1)
attn_hmma_kernel()
{
    extern __shared__ char sm[];
    __nv_bfloat16* qh = (__nv_bfloat16*)(sm + AQ_H);
    __nv_bfloat16* ql = (__nv_bfloat16*)(sm + AQ_L);
    __nv_bfloat16* kh = (__nv_bfloat16*)(sm + AK_H);
    __nv_bfloat16* kl = (__nv_bfloat16*)(sm + AK_L);
    __nv_bfloat16* vh = (__nv_bfloat16*)(sm + AVH_);
    __nv_bfloat16* vl = (__nv_bfloat16*)(sm + AVL_);
    __nv_bfloat16* Sh = (__nv_bfloat16*)(sm + AS_H);
    __nv_bfloat16* Sl = (__nv_bfloat16*)(sm + AS_L);
    float* Afp  = (float*)(sm + AA_);      // 128 x 136 fp32
    float* Yst  = (float*)(sm + AA_);      // later 128 x 68 fp32
    float* den2 = (float*)(sm + ADEN2);    // 512 partials
    float* den  = (float*)(sm + ADEN);
    float* kp   = (float*)(sm + AKP);
    __nv_bfloat16* Ahi = (__nv_bfloat16*)(sm + A_HI_OFF);
    __nv_bfloat16* Alo = (__nv_bfloat16*)(sm + A_LO_OFF);

    const int tid = threadIdx.x;
    const int wid = tid >> 5;
    const int bh = blockIdx.x >> 4, c = blockIdx.x & 15;
    const int wr = wid >> 2, wc = wid & 3;   // 4x4 warp grid

    const size_t gb = ((size_t)bh * T_ + c * L_) * 64;

    // load q/k/v hi/lo (1024 uint4 per plane, 2 per thread)
#pragma unroll
    for (int q = 0; q < 2; q++) {
        int f = q * 512 + tid;
        int r = f >> 3, c8 = (f & 7) * 8;
        int so = r * 72 + c8;
        *(uint4*)&qh[so] = *(const uint4*)&g_qh[gb + (size_t)f * 8];
        *(uint4*)&ql[so] = *(const uint4*)&g_ql[gb + (size_t)f * 8];
        *(uint4*)&kh[so] = *(const uint4*)&g_kh[gb + (size_t)f * 8];
        *(uint4*)&kl[so] = *(const uint4*)&g_kl[gb + (size_t)f * 8];
        *(uint4*)&vh[so] = *(const uint4*)&g_vh[gb + (size_t)f * 8];
        *(uint4*)&vl[so] = *(const uint4*)&g_vl[gb + (size_t)f * 8];
    }
    {
        size_t sb = (size_t)(bh * NC_ + c) * 4096;
        for (int e = tid; e < 4096; e += 512) {
            int i = e >> 6, j = e & 63;
            float v = g_kv[sb + e];
            __nv_bfloat16 h = __float2bfloat16(v);
            Sh[i * 72 + j] = h;
            Sl[i * 72 + j] = __float2bfloat16(v - __bfloat162float(h));
        }
        if (tid < 64) kp[tid] = g_ks[(size_t)(bh * NC_ + c) * 64 + tid];
    }
    __syncthreads();

    // nAcc = q @ S : output 128x64, warp tile 32(M) x 16(N) -> acc[2]
    wmma::fragment<wmma::accumulator, 16, 16, 16, float> nAcc[2];
    wmma::fill_fragment(nAcc[0], 0.f);
    wmma::fill_fragment(nAcc[1], 0.f);

#pragma unroll
    for (int kk = 0; kk < 64; kk += 16) {
        wmma::fragment<wmma::matrix_a, 16, 16, 16, __nv_bfloat16, wmma::row_major> aH[2], aL[2];
#pragma unroll
        for (int i = 0; i < 2; i++) {
            wmma::load_matrix_sync(aH[i], &qh[(wr * 32 + i * 16) * 72 + kk], 72);
            wmma::load_matrix_sync(aL[i], &ql[(wr * 32 + i * 16) * 72 + kk], 72);
        }
        wmma::fragment<wmma::matrix_b, 16, 16, 16, __nv_bfloat16, wmma::row_major> bH, bL;
        wmma::load_matrix_sync(bH, &Sh[kk * 72 + wc * 16], 72);
        wmma::load_matrix_sync(bL, &Sl[kk * 72 + wc * 16], 72);
#pragma unroll
        for (int i = 0; i < 2; i++) {
            wmma::mma_sync(nAcc[i], aH[i], bH, nAcc[i]);
            wmma::mma_sync(nAcc[i], aH[i], bL, nAcc[i]);
            wmma::mma_sync(nAcc[i], aL[i], bH, nAcc[i]);
        }
    }

    // A = q @ k^T : output 128x128, warp tile 32x32 -> aAcc[2][2]
    {
        wmma::fragment<wmma::accumulator, 16, 16, 16, float> aAcc[2][2];
#pragma unroll
        for (int i = 0; i < 2; i++)
#pragma unroll
            for (int j = 0; j < 2; j++) wmma::fill_fragment(aAcc[i][j], 0.f);

#pragma unroll
        for (int kk = 0; kk < 64; kk += 16) {
            wmma::fragment<wmma::matrix_a, 16, 16, 16, __nv_bfloat16, wmma::row_major> aH[2], aL[2];
#pragma unroll
            for (int i = 0; i < 2; i++) {
                wmma::load_matrix_sync(aH[i], &qh[(wr * 32 + i * 16) * 72 + kk], 72);
                wmma::load_matrix_sync(aL[i], &ql[(wr * 32 + i * 16) * 72 + kk], 72);
            }
#pragma unroll
            for (int j = 0; j < 2; j++) {
                wmma::fragment<wmma::matrix_b, 16, 16, 16, __nv_bfloat16, wmma::col_major> bH, bL;
                wmma::load_matrix_sync(bH, &kh[(wc * 32 + j * 16) * 72 + kk], 72);
                wmma::load_matrix_sync(bL, &kl[(wc * 32 + j * 16) * 72 + kk], 72);
#pragma unroll
                for (int i = 0; i < 2; i++) {
                    wmma::mma_sync(aAcc[i][j], aH[i], bH, aAcc[i][j]);
                    wmma::mma_sync(aAcc[i][j], aH[i], bL, aAcc[i][j]);
                    wmma::mma_sync(aAcc[i][j], aL[i], bH, aAcc[i][j]);
                }
            }
        }
#pragma unroll
        for (int i = 0; i < 2; i++)
#pragma unroll
            for (int j = 0; j < 2; j++)
                wmma::store_matrix_sync(&Afp[(wr * 32 + i * 16) * 136 + wc * 32 + j * 16],
                                        aAcc[i][j], 136, wmma::mem_row_major);
    }
    __syncthreads();

    // masked rowsum partials: t = tid>>2, quarter = tid&3 covers 32 cols
    {
        int t = tid >> 2, qt = tid & 3;
        float s = 0.f;
        for (int s2 = 0; s2 < 32; s2++) {
            int sg = qt * 32 + s2;
            if (sg <= t) s += Afp[t * 136 + sg];
        }
        den2[tid] = s;
    }
    __syncthreads();
    if (tid < 128) {
        float s = den2[tid * 4] + den2[tid * 4 + 1] + den2[tid * 4 + 2] + den2[tid * 4 + 3];
        for (int d = 0; d < 64; d++)
            s += (__bfloat162float(qh[tid * 72 + d]) +
                  __bfloat162float(ql[tid * 72 + d])) * kp[d];
        den[tid] = fmaxf(s, EPS_);
    }
    __syncthreads();
    // mask + split A -> bf16 hi/lo (vectorized x2)
    for (int e2 = tid; e2 < 128 * 64; e2 += 512) {
        int t = e2 >> 6, s2 = (e2 & 63) * 2;
        float v0 = (s2     <= t) ? Afp[t * 136 + s2]     : 0.f;
        float v1 = (s2 + 1 <= t) ? Afp[t * 136 + s2 + 1] : 0.f;
        __nv_bfloat16 h0 = __float2bfloat16(v0);
        __nv_bfloat16 h1 = __float2bfloat16(v1);
        __nv_bfloat162 hh; hh.x = h0; hh.y = h1;
        __nv_bfloat162 ll;
        ll.x = __float2bfloat16(v0 - __bfloat162float(h0));
        ll.y = __float2bfloat16(v1 - __bfloat162float(h1));
        *(__nv_bfloat162*)&Ahi[t * 136 + s2] = hh;
        *(__nv_bfloat162*)&Alo[t * 136 + s2] = ll;
    }
    __syncthreads();

    // nAcc += A @ V  (K=128)
#pragma unroll
    for (int kk = 0; kk < 128; kk += 16) {
        wmma::fragment<wmma::matrix_a, 16, 16, 16, __nv_bfloat16, wmma::row_major> aH[2], aL[2];
#pragma unroll
        for (int i = 0; i < 2; i++) {
            wmma::load_matrix_sync(aH[i], &Ahi[(wr * 32 + i * 16) * 136 + kk], 136);
            wmma::load_matrix_sync(aL[i], &Alo[(wr * 32 + i * 16) * 136 + kk], 136);
        }
        wmma::fragment<wmma::matrix_b, 16, 16, 16, __nv_bfloat16, wmma::row_major> bH, bL;
        wmma::load_matrix_sync(bH, &vh[kk * 72 + wc * 16], 72);
        wmma::load_matrix_sync(bL, &vl[kk * 72 + wc * 16], 72);
#pragma unroll
        for (int i = 0; i < 2; i++) {
            wmma::mma_sync(nAcc[i], aH[i], bH, nAcc[i]);
            wmma::mma_sync(nAcc[i], aH[i], bL, nAcc[i]);
            wmma::mma_sync(nAcc[i], aL[i], bH, nAcc[i]);
        }
    }
    __syncthreads();
#pragma unroll
    for (int i = 0; i < 2; i++)
        wmma::store_matrix_sync(&Yst[(wr * 32 + i * 16) * 68 + wc * 16],
                                nAcc[i], 68, wmma::mem_row_major);
    __syncthreads();

    // y = num/den -> bf16 hi/lo
    {
        const int bidx = bh >> 3, h = bh & 7;
        int t = tid >> 2, qt = tid & 3;
        float inv = 1.f / den[t];
        int tg = c * L_ + t;
        size_t yb = ((size_t)bidx * T_ + tg) * C_ + h * 64 + qt * 16;
        for (int c2 = 0; c2 < 16; c2 += 2) {
            float v0 = Yst[t * 68 + qt * 16 + c2]     * inv;
            float v1 = Yst[t * 68 + qt * 16 + c2 + 1] * inv;
            split_store(g_yhi, g_ylo, yb + c2, v0, v1);
        }
    }
}

// ---------------------------------------------------------------------------
extern "C" void kernel_launch(void* const* d_in, const int* in_sizes, int n_in,
                              void* d_out, int out_size)
{
    const float* x     = (const float*)d_in[0];
    const float* am    = (const float*)d_in[1];
    const float* wqkv  = (const float*)d_in[2];
    const float* bqkv  = (const float*)d_in[3];
    const float* wproj = (const float*)d_in[4];
    const float* bproj = (const float*)d_in[5];
    float* out = (float*)d_out;

    static bool attr_set = false;
    if (!attr_set) {
        cudaFuncSetAttribute(wmma_gemm_kernel<0>,
                             cudaFuncAttributeMaxDynamicSharedMemorySize, G_SMEM);
        cudaFuncSetAttribute(wmma_gemm_kernel<1>,
                             cudaFuncAttributeMaxDynamicSharedMemorySize, G_SMEM);
        cudaFuncSetAttribute(chunk_kv_hmma,
                             cudaFuncAttributeMaxDynamicSharedMemorySize, CK_SMEM);
        cudaFuncSetAttribute(attn_hmma_kernel,
                             cudaFuncAttributeMaxDynamicSharedMemorySize, ATT_SMEM);
        attr_set = true;
    }

    __nv_bfloat16 *xhi, *xlo, *wqh, *wql, *wph, *wpl, *yhi, *ylo;
    cudaGetSymbolAddress((void**)&xhi, g_xhi);
    cudaGetSymbolAddress((void**)&xlo, g_xlo);
    cudaGetSymbolAddress((void**)&wqh, g_wqh);
    cudaGetSymbolAddress((void**)&wql, g_wql);
    cudaGetSymbolAddress((void**)&wph, g_wph);
    cudaGetSymbolAddress((void**)&wpl, g_wpl);
    cudaGetSymbolAddress((void**)&yhi, g_yhi);
    cudaGetSymbolAddress((void**)&ylo, g_ylo);

    const int nsplit4 = NX4 + NQ4 + NP4;
    fused_split_kernel<<<(nsplit4 + 255) / 256, 256>>>(x, wqkv, wproj);

    dim3 g1(M_ / 128, 1536 / 128);
    wmma_gemm_kernel<0><<<g1, 256, G_SMEM>>>(xhi, xlo, wqh, wql, bqkv, am, nullptr);

    chunk_kv_hmma<<<BH_ * NC_, 256, CK_SMEM>>>();

    dim3 gs(17, BH_);
    chunk_scan_fast<<<gs, 256>>>();

    attn_hmma_kernel<<<BH_ * NC_, 512, ATT_SMEM>>>();

    dim3 g5(M_ / 128, 512 / 128);
    wmma_gemm_kernel<1><<<g5, 256, G_SMEM>>>(yhi, ylo, wph, wpl, bproj, nullptr, out);
}